// round 16
// baseline (speedup 1.0000x reference)
#include <cuda_runtime.h>
#include <cuda_fp16.h>
#include <cstdint>

// C[b] = A[b](1024x64) @ B[b](64x1024), fp32, b in [0,24).
// fp16 mma.sync m16n8k16 (fp32 accum), CTA 128m x 256n (two n-tiles),
// warp tile 32x64, permuted-B epilogue (STG.128), single barrier.
// Round 16: A fragments hoisted into registers before the tile loop —
// loaded once via ldmatrix, reused for both n-tiles (A is tile-invariant).

#define M_DIM 1024
#define N_DIM 1024
#define K_DIM 64
#define BATCH 24
#define THREADS 256

#define SMEM_A   0        // 128 x 64 fp16, SW128 rows (16 KB)
#define SMEM_B1  16384    // tile-1 B: 128 x 64 fp16 transposed+permuted
#define SMEM_B2  32768    // tile-2 B
#define SMEM_TOTAL 49152

#define SW128(o) ((o) ^ (((o) >> 3) & 0x70))

__device__ __forceinline__ uint32_t smem_u32(const void* p) {
    uint32_t a;
    asm("{ .reg .u64 t; cvta.to.shared.u64 t, %1; cvt.u32.u64 %0, t; }"
        : "=r"(a) : "l"(p));
    return a;
}

__device__ __forceinline__ void ldsm_x4(uint32_t* r, uint32_t addr) {
    asm volatile("ldmatrix.sync.aligned.m8n8.x4.shared.b16 {%0,%1,%2,%3}, [%4];"
                 : "=r"(r[0]), "=r"(r[1]), "=r"(r[2]), "=r"(r[3])
                 : "r"(addr));
}

__device__ __forceinline__ void mma_fp16(float* c, const uint32_t* a,
                                         uint32_t b0, uint32_t b1) {
    asm volatile(
        "mma.sync.aligned.m16n8k16.row.col.f32.f16.f16.f32 "
        "{%0,%1,%2,%3}, {%4,%5,%6,%7}, {%8,%9}, {%0,%1,%2,%3};"
        : "+f"(c[0]), "+f"(c[1]), "+f"(c[2]), "+f"(c[3])
        : "r"(a[0]), "r"(a[1]), "r"(a[2]), "r"(a[3]), "r"(b0), "r"(b1));
}

__device__ __forceinline__ uint32_t packh2(float a, float b) {
    uint32_t r;
    asm("{ .reg .f16 lo, hi;\n\t"
        "  cvt.rn.f16.f32 lo, %1;\n\t"
        "  cvt.rn.f16.f32 hi, %2;\n\t"
        "  mov.b32 %0, {lo, hi}; }"
        : "=r"(r) : "f"(a), "f"(b));
    return r;
}

// Column permutation within a 64-col warp block (round 9).
__device__ __forceinline__ int bperm(int gb) {
    const int ni = (((gb >> 4) & 3) << 1) | ((gb >> 1) & 1);
    const int tq = (gb >> 2) & 3;
    return ni * 8 + tq * 2 + (gb & 1);
}

// Convert an 8k x 4n fp32 register block to fp16, store transposed+permuted.
__device__ __forceinline__ void store_b_block(char* smem, uint32_t buf_off,
                                              int nq, int kb, const float4* v) {
    const float* vf = reinterpret_cast<const float*>(v);
#pragma unroll
    for (int e = 0; e < 4; e++) {
        const int n = nq * 4 + e;
        const int srow = (n & 64) + bperm(n & 63);
        uint4 h;
        h.x = packh2(vf[0 * 4 + e], vf[1 * 4 + e]);
        h.y = packh2(vf[2 * 4 + e], vf[3 * 4 + e]);
        h.z = packh2(vf[4 * 4 + e], vf[5 * 4 + e]);
        h.w = packh2(vf[6 * 4 + e], vf[7 * 4 + e]);
        const uint32_t off = SW128((uint32_t)(srow * 128 + kb * 16));
        *reinterpret_cast<uint4*>(smem + buf_off + off) = h;
    }
}

__global__ void __launch_bounds__(THREADS, 2)
bmm_fp16_kernel(const float* __restrict__ A,
                const float* __restrict__ B,
                float* __restrict__ C) {
    extern __shared__ __align__(1024) char smem[];
    const uint32_t smem_base = smem_u32(smem);
    const int tid = threadIdx.x;
    const int wid = tid >> 5;
    const int lid = tid & 31;

    const int bz    = blockIdx.z;
    const int row0  = blockIdx.y * 128;
    const int col0a = blockIdx.x * 256;
    const int col0b = col0a + 128;

    const float* __restrict__ Ab = A + (size_t)bz * M_DIM * K_DIM;
    const float* __restrict__ Bb = B + (size_t)bz * K_DIM * N_DIM;
    float*       __restrict__ Cb = C + (size_t)bz * M_DIM * N_DIM;

    const int nq = tid & 31;    // B: n-quad
    const int kb = tid >> 5;    // B: k-group of 8

    // ---- issue A + B1 LDGs together (high MLP) ----
    float4 va[8];
#pragma unroll
    for (int i = 0; i < 8; i++) {
        const int f = tid + i * THREADS;
        va[i] = *reinterpret_cast<const float4*>(
            &Ab[(size_t)(row0 + (f >> 4)) * K_DIM + (f & 15) * 4]);
    }
    float4 vb[8];
#pragma unroll
    for (int j = 0; j < 8; j++)
        vb[j] = *reinterpret_cast<const float4*>(
            &Bb[(size_t)(kb * 8 + j) * N_DIM + col0a + nq * 4]);

    // ---- convert A while B1 still lands ----
#pragma unroll
    for (int i = 0; i < 8; i++) {
        const int f = tid + i * THREADS;
        const int r = f >> 4;
        const int q = f & 15;
        uint2 h = make_uint2(packh2(va[i].x, va[i].y), packh2(va[i].z, va[i].w));
        const uint32_t off = SW128((uint32_t)(r * 128 + q * 8));
        *reinterpret_cast<uint2*>(smem + SMEM_A + off) = h;
    }

    // ---- convert B1, then issue+convert B2 ----
    store_b_block(smem, SMEM_B1, nq, kb, vb);
#pragma unroll
    for (int j = 0; j < 8; j++)
        vb[j] = *reinterpret_cast<const float4*>(
            &Bb[(size_t)(kb * 8 + j) * N_DIM + col0b + nq * 4]);
    store_b_block(smem, SMEM_B2, nq, kb, vb);

    __syncthreads();   // the ONLY barrier

    // ---- warp tiling ----
    const int warp_m = wid & 3;
    const int warp_n = wid >> 2;
    const int g = lid >> 3;
    const int r8 = lid & 7;
    const int a_row_l = warp_m * 32 + (g & 1) * 8 + r8;
    const int a_kb_l  = (g >> 1) * 16;
    const int b_row_l = warp_n * 64 + (g >> 1) * 8 + r8;
    const int b_kb_l  = (g & 1) * 16;
    const int tq = lid & 3;
    const int tr = lid >> 2;

    // ---- A fragments: loaded ONCE, reused across both n-tiles (32 regs) ----
    uint32_t af[2][4][4];   // [mi][ks][reg]
#pragma unroll
    for (int ks = 0; ks < 4; ks++) {
        ldsm_x4(af[0][ks], smem_base + SMEM_A +
                           SW128((uint32_t)(a_row_l * 128 + ks * 32 + a_kb_l)));
        ldsm_x4(af[1][ks], smem_base + SMEM_A +
                           SW128((uint32_t)((a_row_l + 16) * 128 + ks * 32 + a_kb_l)));
    }

#pragma unroll
    for (int t = 0; t < 2; t++) {
        const uint32_t bbuf = smem_base + (t ? SMEM_B2 : SMEM_B1);

        float acc[2][8][4];
#pragma unroll
        for (int mi = 0; mi < 2; mi++)
#pragma unroll
            for (int ni = 0; ni < 8; ni++)
#pragma unroll
                for (int j = 0; j < 4; j++) acc[mi][ni][j] = 0.0f;

#pragma unroll
        for (int ks = 0; ks < 4; ks++) {
#pragma unroll
            for (int h = 0; h < 2; h++) {
                uint32_t bf[4][2];
#pragma unroll
                for (int q2 = 0; q2 < 2; q2++) {
                    uint32_t rr[4];
                    ldsm_x4(rr, bbuf +
                                SW128((uint32_t)((b_row_l + (h * 2 + q2) * 16) * 128 +
                                                 ks * 32 + b_kb_l)));
                    bf[q2 * 2 + 0][0] = rr[0]; bf[q2 * 2 + 0][1] = rr[1];
                    bf[q2 * 2 + 1][0] = rr[2]; bf[q2 * 2 + 1][1] = rr[3];
                }
#pragma unroll
                for (int mi = 0; mi < 2; mi++)
#pragma unroll
                    for (int ni = 0; ni < 4; ni++)
                        mma_fp16(acc[mi][h * 4 + ni], af[mi][ks],
                                 bf[ni][0], bf[ni][1]);
            }
        }

        // ---- epilogue: contiguous STG.128 (permuted B) ----
        const int col0 = t == 0 ? col0a : col0b;
#pragma unroll
        for (int mi = 0; mi < 2; mi++) {
            const int rbase = row0 + warp_m * 32 + mi * 16 + tr;
            float* c0 = &Cb[(size_t)rbase * N_DIM + col0 + warp_n * 64 + tq * 4];
            float* c1 = c0 + 8 * N_DIM;
#pragma unroll
            for (int c = 0; c < 4; c++) {
                float4 v0 = make_float4(acc[mi][2 * c][0], acc[mi][2 * c][1],
                                        acc[mi][2 * c + 1][0], acc[mi][2 * c + 1][1]);
                float4 v1 = make_float4(acc[mi][2 * c][2], acc[mi][2 * c][3],
                                        acc[mi][2 * c + 1][2], acc[mi][2 * c + 1][3]);
                *reinterpret_cast<float4*>(c0 + c * 16) = v0;
                *reinterpret_cast<float4*>(c1 + c * 16) = v1;
            }
        }
    }
}

extern "C" void kernel_launch(void* const* d_in, const int* in_sizes, int n_in,
                              void* d_out, int out_size) {
    const float* A = (const float*)d_in[0];   // [2,12,1024,64]
    const float* B = (const float*)d_in[1];   // [2,12,64,1024]
    float* C = (float*)d_out;                 // [2,12,1024,1024]

    cudaFuncSetAttribute(bmm_fp16_kernel,
                         cudaFuncAttributeMaxDynamicSharedMemorySize, SMEM_TOTAL);
    dim3 grid(N_DIM / 256, M_DIM / 128, BATCH);  // (4, 8, 24)
    bmm_fp16_kernel<<<grid, THREADS, SMEM_TOTAL>>>(A, B, C);
}

// round 17
// speedup vs baseline: 1.0011x; 1.0011x over previous
#include <cuda_runtime.h>
#include <cuda_fp16.h>
#include <cstdint>

// C[b] = A[b](1024x64) @ B[b](64x1024), fp32, b in [0,24).
// fp16 mma.sync m16n8k16 (fp32 accum), CTA 128m x 256n (two n-tiles),
// warp tile 32x64, permuted-B epilogue (STG.128), single barrier.
// Round 17: each tile computed in two ni-halves (32 live acc regs instead of
// 64) -> peak registers ~70 -> 3 CTAs/SM (24 warps). Warp tile / CTA tile /
// reuse unchanged; mainloop A-ldsm re-read per half (+3% total wavefronts).

#define M_DIM 1024
#define N_DIM 1024
#define K_DIM 64
#define BATCH 24
#define THREADS 256

#define SMEM_A   0        // 128 x 64 fp16, SW128 rows (16 KB)
#define SMEM_B1  16384    // tile-1 B: 128 x 64 fp16 transposed+permuted
#define SMEM_B2  32768    // tile-2 B
#define SMEM_TOTAL 49152  // 48 KB x 3 CTAs = 144 KB <= 228 KB

#define SW128(o) ((o) ^ (((o) >> 3) & 0x70))

__device__ __forceinline__ uint32_t smem_u32(const void* p) {
    uint32_t a;
    asm("{ .reg .u64 t; cvta.to.shared.u64 t, %1; cvt.u32.u64 %0, t; }"
        : "=r"(a) : "l"(p));
    return a;
}

__device__ __forceinline__ void ldsm_x4(uint32_t* r, uint32_t addr) {
    asm volatile("ldmatrix.sync.aligned.m8n8.x4.shared.b16 {%0,%1,%2,%3}, [%4];"
                 : "=r"(r[0]), "=r"(r[1]), "=r"(r[2]), "=r"(r[3])
                 : "r"(addr));
}

__device__ __forceinline__ void mma_fp16(float* c, const uint32_t* a,
                                         uint32_t b0, uint32_t b1) {
    asm volatile(
        "mma.sync.aligned.m16n8k16.row.col.f32.f16.f16.f32 "
        "{%0,%1,%2,%3}, {%4,%5,%6,%7}, {%8,%9}, {%0,%1,%2,%3};"
        : "+f"(c[0]), "+f"(c[1]), "+f"(c[2]), "+f"(c[3])
        : "r"(a[0]), "r"(a[1]), "r"(a[2]), "r"(a[3]), "r"(b0), "r"(b1));
}

__device__ __forceinline__ uint32_t packh2(float a, float b) {
    uint32_t r;
    asm("{ .reg .f16 lo, hi;\n\t"
        "  cvt.rn.f16.f32 lo, %1;\n\t"
        "  cvt.rn.f16.f32 hi, %2;\n\t"
        "  mov.b32 %0, {lo, hi}; }"
        : "=r"(r) : "f"(a), "f"(b));
    return r;
}

// Column permutation within a 64-col warp block (round 9):
// frag position p = ni*8 + tq*2 + e  holds global col
//   g = (ni>>1)*16 + tq*4 + (ni&1)*2 + e.
// Note half h (ni in {4h..4h+3}) covers the contiguous global block
//   [h*32, h*32+32)  -> each half has a clean 32-col epilogue.
__device__ __forceinline__ int bperm(int gb) {
    const int ni = (((gb >> 4) & 3) << 1) | ((gb >> 1) & 1);
    const int tq = (gb >> 2) & 3;
    return ni * 8 + tq * 2 + (gb & 1);
}

// Convert an 8k x 4n fp32 register block to fp16, store transposed+permuted.
__device__ __forceinline__ void store_b_block(char* smem, uint32_t buf_off,
                                              int nq, int kb, const float4* v) {
    const float* vf = reinterpret_cast<const float*>(v);
#pragma unroll
    for (int e = 0; e < 4; e++) {
        const int n = nq * 4 + e;
        const int srow = (n & 64) + bperm(n & 63);
        uint4 h;
        h.x = packh2(vf[0 * 4 + e], vf[1 * 4 + e]);
        h.y = packh2(vf[2 * 4 + e], vf[3 * 4 + e]);
        h.z = packh2(vf[4 * 4 + e], vf[5 * 4 + e]);
        h.w = packh2(vf[6 * 4 + e], vf[7 * 4 + e]);
        const uint32_t off = SW128((uint32_t)(srow * 128 + kb * 16));
        *reinterpret_cast<uint4*>(smem + buf_off + off) = h;
    }
}

__global__ void __launch_bounds__(THREADS, 3)
bmm_fp16_kernel(const float* __restrict__ A,
                const float* __restrict__ B,
                float* __restrict__ C) {
    extern __shared__ __align__(1024) char smem[];
    const uint32_t smem_base = smem_u32(smem);
    const int tid = threadIdx.x;
    const int wid = tid >> 5;
    const int lid = tid & 31;

    const int bz    = blockIdx.z;
    const int row0  = blockIdx.y * 128;
    const int col0a = blockIdx.x * 256;
    const int col0b = col0a + 128;

    const float* __restrict__ Ab = A + (size_t)bz * M_DIM * K_DIM;
    const float* __restrict__ Bb = B + (size_t)bz * K_DIM * N_DIM;
    float*       __restrict__ Cb = C + (size_t)bz * M_DIM * N_DIM;

    const int nq = tid & 31;    // B: n-quad
    const int kb = tid >> 5;    // B: k-group of 8

    // ---- issue A + B1 LDGs together (high MLP) ----
    float4 va[8];
#pragma unroll
    for (int i = 0; i < 8; i++) {
        const int f = tid + i * THREADS;
        va[i] = *reinterpret_cast<const float4*>(
            &Ab[(size_t)(row0 + (f >> 4)) * K_DIM + (f & 15) * 4]);
    }
    float4 vb[8];
#pragma unroll
    for (int j = 0; j < 8; j++)
        vb[j] = *reinterpret_cast<const float4*>(
            &Bb[(size_t)(kb * 8 + j) * N_DIM + col0a + nq * 4]);

    // ---- convert A while B1 still lands ----
#pragma unroll
    for (int i = 0; i < 8; i++) {
        const int f = tid + i * THREADS;
        const int r = f >> 4;
        const int q = f & 15;
        uint2 h = make_uint2(packh2(va[i].x, va[i].y), packh2(va[i].z, va[i].w));
        const uint32_t off = SW128((uint32_t)(r * 128 + q * 8));
        *reinterpret_cast<uint2*>(smem + SMEM_A + off) = h;
    }

    // ---- convert B1, then issue+convert B2 ----
    store_b_block(smem, SMEM_B1, nq, kb, vb);
#pragma unroll
    for (int j = 0; j < 8; j++)
        vb[j] = *reinterpret_cast<const float4*>(
            &Bb[(size_t)(kb * 8 + j) * N_DIM + col0b + nq * 4]);
    store_b_block(smem, SMEM_B2, nq, kb, vb);

    __syncthreads();   // the ONLY barrier

    // ---- warp tiling ----
    const int warp_m = wid & 3;
    const int warp_n = wid >> 2;
    const int g = lid >> 3;
    const int r8 = lid & 7;
    const int a_row_l = warp_m * 32 + (g & 1) * 8 + r8;
    const int a_kb_l  = (g >> 1) * 16;
    const int b_row_l = warp_n * 64 + (g >> 1) * 8 + r8;
    const int b_kb_l  = (g & 1) * 16;
    const int tq = lid & 3;
    const int tr = lid >> 2;

#pragma unroll
    for (int t = 0; t < 2; t++) {
        const uint32_t bbuf = smem_base + (t ? SMEM_B2 : SMEM_B1);
        const int col0 = t == 0 ? col0a : col0b;

        // process tile in two ni-halves: only 32 acc regs live at a time
#pragma unroll
        for (int h = 0; h < 2; h++) {
            float acc[2][4][4];
#pragma unroll
            for (int mi = 0; mi < 2; mi++)
#pragma unroll
                for (int ni = 0; ni < 4; ni++)
#pragma unroll
                    for (int j = 0; j < 4; j++) acc[mi][ni][j] = 0.0f;

#pragma unroll
            for (int ks = 0; ks < 4; ks++) {
                uint32_t af[2][4];
                ldsm_x4(af[0], smem_base + SMEM_A +
                               SW128((uint32_t)(a_row_l * 128 + ks * 32 + a_kb_l)));
                ldsm_x4(af[1], smem_base + SMEM_A +
                               SW128((uint32_t)((a_row_l + 16) * 128 + ks * 32 + a_kb_l)));
                uint32_t bf[4][2];
#pragma unroll
                for (int q2 = 0; q2 < 2; q2++) {
                    uint32_t rr[4];
                    ldsm_x4(rr, bbuf +
                                SW128((uint32_t)((b_row_l + (h * 2 + q2) * 16) * 128 +
                                                 ks * 32 + b_kb_l)));
                    bf[q2 * 2 + 0][0] = rr[0]; bf[q2 * 2 + 0][1] = rr[1];
                    bf[q2 * 2 + 1][0] = rr[2]; bf[q2 * 2 + 1][1] = rr[3];
                }
#pragma unroll
                for (int mi = 0; mi < 2; mi++)
#pragma unroll
                    for (int ni = 0; ni < 4; ni++)
                        mma_fp16(acc[mi][ni], af[mi], bf[ni][0], bf[ni][1]);
            }

            // ---- epilogue for this half: contiguous 32-col block ----
#pragma unroll
            for (int mi = 0; mi < 2; mi++) {
                const int rbase = row0 + warp_m * 32 + mi * 16 + tr;
                float* c0 = &Cb[(size_t)rbase * N_DIM + col0 + warp_n * 64 +
                                h * 32 + tq * 4];
                float* c1 = c0 + 8 * N_DIM;
#pragma unroll
                for (int c = 0; c < 2; c++) {
                    float4 v0 = make_float4(acc[mi][2 * c][0], acc[mi][2 * c][1],
                                            acc[mi][2 * c + 1][0], acc[mi][2 * c + 1][1]);
                    float4 v1 = make_float4(acc[mi][2 * c][2], acc[mi][2 * c][3],
                                            acc[mi][2 * c + 1][2], acc[mi][2 * c + 1][3]);
                    *reinterpret_cast<float4*>(c0 + c * 16) = v0;
                    *reinterpret_cast<float4*>(c1 + c * 16) = v1;
                }
            }
        }
    }
}

extern "C" void kernel_launch(void* const* d_in, const int* in_sizes, int n_in,
                              void* d_out, int out_size) {
    const float* A = (const float*)d_in[0];   // [2,12,1024,64]
    const float* B = (const float*)d_in[1];   // [2,12,64,1024]
    float* C = (float*)d_out;                 // [2,12,1024,1024]

    cudaFuncSetAttribute(bmm_fp16_kernel,
                         cudaFuncAttributeMaxDynamicSharedMemorySize, SMEM_TOTAL);
    dim3 grid(N_DIM / 256, M_DIM / 128, BATCH);  // (4, 8, 24)
    bmm_fp16_kernel<<<grid, THREADS, SMEM_TOTAL>>>(A, B, C);
}